// round 2
// baseline (speedup 1.0000x reference)
#include <cuda_runtime.h>
#include <math.h>

#define LOG2E_F 1.4426950408889634f

// ---------------- scratch (static device globals; no allocs) ----------------
__device__ float g_f[32 * 1024 * 128];       // f = fi@Wf + bf           16 MB
__device__ float g_K[32 * 64 * 1024];        // M' (base-2 scaled) -> K~  8 MB
__device__ float g_mrow[32 * 64];            // per-row max of M'
__device__ float g_r[32 * 65];               // Sinkhorn row scalings
__device__ float g_c[32 * 1024];             // Sinkhorn col scalings
__device__ float g_vpart[32 * 8 * 64 * 128]; // split-K partials of p@f   8.4 MB
__device__ float g_pspart[32 * 8 * 64];      // split-K partials of rowsum(p)

__device__ __forceinline__ float warpSum(float v) {
    #pragma unroll
    for (int o = 16; o > 0; o >>= 1) v += __shfl_xor_sync(0xffffffffu, v, o);
    return v;
}
__device__ __forceinline__ float warpMax(float v) {
    #pragma unroll
    for (int o = 16; o > 0; o >>= 1) v = fmaxf(v, __shfl_xor_sync(0xffffffffu, v, o));
    return v;
}

// ---------------------------------------------------------------------------
// GEMM A: for each batch, fi (1024x768) @ [Wf | Ws] (768x192).
// cols 0..127 -> g_f[b][n][c] (+bf); cols 128..191 -> M' transposed into
// g_K[b][k][n] = (acc+bs[k]) * sharpness * (1/REG) * LOG2E  (base-2 scaled).
// BM=128 (n), BN=64 (col), BK=16; 256 threads; 8x4 microtile.
// ---------------------------------------------------------------------------
__global__ __launch_bounds__(256) void gemmA(
    const float* __restrict__ x,
    const float* __restrict__ Wf, const float* __restrict__ bf,
    const float* __restrict__ Ws, const float* __restrict__ bs,
    const float* __restrict__ sharp)
{
    __shared__ float As[16][128];
    __shared__ float Bs[16][64];

    const int b  = blockIdx.z;
    const int nt = blockIdx.y;   // 0..7   (n tile of 128)
    const int ct = blockIdx.x;   // 0..2   (col tile of 64)
    const int tid = threadIdx.x;
    const int tx = tid & 15, ty = tid >> 4;

    const float* A = x + (size_t)b * 1025 * 768 + 768 + (size_t)nt * 128 * 768;

    const int lm  = tid >> 1;         // 0..127 A row within tile
    const int lk  = (tid & 1) * 8;    // 0 or 8
    const int bkr = tid >> 4;         // 0..15 B row within k-chunk
    const int bc4 = (tid & 15) * 4;   // 0..60

    float acc[8][4];
    #pragma unroll
    for (int i = 0; i < 8; i++)
        #pragma unroll
        for (int j = 0; j < 4; j++) acc[i][j] = 0.0f;

    for (int k0 = 0; k0 < 768; k0 += 16) {
        float4 a0 = *(const float4*)(A + (size_t)lm * 768 + k0 + lk);
        float4 a1 = *(const float4*)(A + (size_t)lm * 768 + k0 + lk + 4);
        float4 bv;
        if (ct < 2) bv = *(const float4*)(Wf + (size_t)(k0 + bkr) * 128 + ct * 64 + bc4);
        else        bv = *(const float4*)(Ws + (size_t)(k0 + bkr) * 64 + bc4);

        __syncthreads();
        As[lk + 0][lm] = a0.x; As[lk + 1][lm] = a0.y;
        As[lk + 2][lm] = a0.z; As[lk + 3][lm] = a0.w;
        As[lk + 4][lm] = a1.x; As[lk + 5][lm] = a1.y;
        As[lk + 6][lm] = a1.z; As[lk + 7][lm] = a1.w;
        *(float4*)&Bs[bkr][bc4] = bv;
        __syncthreads();

        #pragma unroll
        for (int kk = 0; kk < 16; kk++) {
            float4 av0 = *(const float4*)&As[kk][ty * 8];
            float4 av1 = *(const float4*)&As[kk][ty * 8 + 4];
            float4 bb  = *(const float4*)&Bs[kk][tx * 4];
            float a8[8] = {av0.x, av0.y, av0.z, av0.w, av1.x, av1.y, av1.z, av1.w};
            float b4[4] = {bb.x, bb.y, bb.z, bb.w};
            #pragma unroll
            for (int i = 0; i < 8; i++)
                #pragma unroll
                for (int j = 0; j < 4; j++)
                    acc[i][j] = fmaf(a8[i], b4[j], acc[i][j]);
        }
    }

    const int nbase = nt * 128 + ty * 8;
    if (ct < 2) {
        #pragma unroll
        for (int i = 0; i < 8; i++) {
            int c = ct * 64 + tx * 4;
            float4 v = make_float4(acc[i][0] + bf[c + 0], acc[i][1] + bf[c + 1],
                                   acc[i][2] + bf[c + 2], acc[i][3] + bf[c + 3]);
            *(float4*)(g_f + ((size_t)(b * 1024 + nbase + i)) * 128 + c) = v;
        }
    } else {
        const float scl = sharp[0] * 10.0f * LOG2E_F;   // sharpness/REG * log2(e)
        #pragma unroll
        for (int j = 0; j < 4; j++) {
            int k = tx * 4 + j;
            float bias = bs[k];
            float4 v0 = make_float4((acc[0][j] + bias) * scl, (acc[1][j] + bias) * scl,
                                    (acc[2][j] + bias) * scl, (acc[3][j] + bias) * scl);
            float4 v1 = make_float4((acc[4][j] + bias) * scl, (acc[5][j] + bias) * scl,
                                    (acc[6][j] + bias) * scl, (acc[7][j] + bias) * scl);
            float* dst = g_K + ((size_t)(b * 64 + k)) * 1024 + nbase;
            *(float4*)(dst)     = v0;
            *(float4*)(dst + 4) = v1;
        }
    }
}

// ------------------------- row max of M' (per b,k) ---------------------------
__global__ __launch_bounds__(1024) void rowmaxK()
{
    const int b = blockIdx.y;
    const int w = threadIdx.x >> 5, l = threadIdx.x & 31;
    const int k = blockIdx.x * 32 + w;
    const float* row = g_K + ((size_t)(b * 64 + k)) * 1024;
    float m = -INFINITY;
    #pragma unroll 8
    for (int n = l; n < 1024; n += 32) m = fmaxf(m, row[n]);
    m = warpMax(m);
    if (l == 0) g_mrow[b * 64 + k] = m;
}

// --------------------- K~ = exp2(M' - rowmax), in place ----------------------
__global__ __launch_bounds__(1024) void expK()
{
    const int i = blockIdx.x * 1024 + threadIdx.x;   // 32*64*1024 elements
    const int row = i >> 10;                          // = b*64 + k
    g_K[i] = exp2f(g_K[i] - g_mrow[row]);
}

__global__ __launch_bounds__(1024) void initC()
{
    g_c[blockIdx.x * 1024 + threadIdx.x] = 1.0f;
}

// r = a / (K~ c) ; r[64] = a / sum(c)   (dust row of K~ is all-ones)
__global__ __launch_bounds__(1024) void sink_r()
{
    const int b = blockIdx.x;
    const int t = threadIdx.x, w = t >> 5, l = t & 31;
    __shared__ float cs[1024];
    __shared__ float red[32];

    float cv = g_c[b * 1024 + t];
    cs[t] = cv;
    float s = warpSum(cv);
    if (l == 0) red[w] = s;
    __syncthreads();
    if (t == 0) {
        float tot = 0.0f;
        #pragma unroll
        for (int i = 0; i < 32; i++) tot += red[i];
        g_r[b * 65 + 64] = (1.0f / 65.0f) / tot;
    }

    #pragma unroll
    for (int rr = 0; rr < 2; rr++) {
        const int k = rr * 32 + w;
        const float* row = g_K + ((size_t)(b * 64 + k)) * 1024;
        float d = 0.0f;
        #pragma unroll 8
        for (int n = l; n < 1024; n += 32) d = fmaf(row[n], cs[n], d);
        d = warpSum(d);
        if (l == 0) g_r[b * 65 + k] = (1.0f / 65.0f) / d;
    }
}

// c = b / (K~^T r + r[64])
__global__ __launch_bounds__(256) void sink_c()
{
    const int b = blockIdx.y;
    const int n = blockIdx.x * 256 + threadIdx.x;
    __shared__ float rs[65];
    if (threadIdx.x < 65) rs[threadIdx.x] = g_r[b * 65 + threadIdx.x];
    __syncthreads();
    const float* Kp = g_K + (size_t)b * 64 * 1024 + n;
    float acc = rs[64];
    #pragma unroll 8
    for (int k = 0; k < 64; k++) acc = fmaf(Kp[(size_t)k * 1024], rs[k], acc);
    g_c[b * 1024 + n] = (1.0f / 1024.0f) / acc;
}

// ---------------------------------------------------------------------------
// GEMM C: partial (64x128) = p_slice @ f_slice over n in [sp*128, sp*128+128),
// with p materialized on the fly as K~ * r * c. Also partial rowsum(p).
// ---------------------------------------------------------------------------
__global__ __launch_bounds__(256) void gemmC()
{
    const int b = blockIdx.y, sp = blockIdx.x;
    const int tid = threadIdx.x;
    const int tx = tid & 15, ty = tid >> 4;
    __shared__ float ps[64][33];
    __shared__ float fs[32][128];

    const int n0 = sp * 128;
    float acc[4][8];
    #pragma unroll
    for (int i = 0; i < 4; i++)
        #pragma unroll
        for (int j = 0; j < 8; j++) acc[i][j] = 0.0f;
    float psum = 0.0f;

    for (int c0 = 0; c0 < 128; c0 += 32) {
        __syncthreads();
        #pragma unroll
        for (int j = 0; j < 2; j++) {
            int idx4 = tid + j * 256;
            int k = idx4 >> 3;
            int nn4 = (idx4 & 7) * 4;
            float4 kv = *(const float4*)(g_K + ((size_t)(b * 64 + k)) * 1024 + n0 + c0 + nn4);
            float4 cv = *(const float4*)(g_c + b * 1024 + n0 + c0 + nn4);
            float rv = __ldg(&g_r[b * 65 + k]);
            ps[k][nn4 + 0] = kv.x * cv.x * rv;
            ps[k][nn4 + 1] = kv.y * cv.y * rv;
            ps[k][nn4 + 2] = kv.z * cv.z * rv;
            ps[k][nn4 + 3] = kv.w * cv.w * rv;
        }
        #pragma unroll
        for (int j = 0; j < 4; j++) {
            int idx4 = tid + j * 256;
            int nn = idx4 >> 5;
            int c4 = (idx4 & 31) * 4;
            *(float4*)&fs[nn][c4] =
                *(const float4*)(g_f + ((size_t)(b * 1024 + n0 + c0 + nn)) * 128 + c4);
        }
        __syncthreads();

        #pragma unroll
        for (int nn = 0; nn < 32; nn++) {
            float a4[4];
            #pragma unroll
            for (int i = 0; i < 4; i++) a4[i] = ps[ty * 4 + i][nn];
            float4 b0 = *(const float4*)&fs[nn][tx * 8];
            float4 b1 = *(const float4*)&fs[nn][tx * 8 + 4];
            float b8[8] = {b0.x, b0.y, b0.z, b0.w, b1.x, b1.y, b1.z, b1.w};
            #pragma unroll
            for (int i = 0; i < 4; i++)
                #pragma unroll
                for (int j = 0; j < 8; j++)
                    acc[i][j] = fmaf(a4[i], b8[j], acc[i][j]);
        }

        if (tid < 64) {
            float s = 0.0f;
            #pragma unroll
            for (int nn = 0; nn < 32; nn++) s += ps[tid][nn];
            psum += s;
        }
    }

    #pragma unroll
    for (int i = 0; i < 4; i++) {
        float* dst = g_vpart + (((size_t)(b * 8 + sp) * 64) + ty * 4 + i) * 128 + tx * 8;
        *(float4*)(dst)     = make_float4(acc[i][0], acc[i][1], acc[i][2], acc[i][3]);
        *(float4*)(dst + 4) = make_float4(acc[i][4], acc[i][5], acc[i][6], acc[i][7]);
    }
    if (tid < 64) g_pspart[(b * 8 + sp) * 64 + tid] = psum;
}

// --------------------------- t = x[:,0] @ Wt + bt ----------------------------
__global__ __launch_bounds__(256) void tK(
    const float* __restrict__ x, const float* __restrict__ Wt,
    const float* __restrict__ bt, float* __restrict__ out)
{
    const int b = blockIdx.x;
    const int c = threadIdx.x;
    __shared__ float xs[768];
    for (int i = c; i < 768; i += 256) xs[i] = x[(size_t)b * 1025 * 768 + i];
    __syncthreads();
    float acc = bt[c];
    #pragma unroll 8
    for (int d = 0; d < 768; d++) acc = fmaf(xs[d], Wt[(size_t)d * 256 + c], acc);
    out[(size_t)b * 8448 + c] = acc;
}

// ------------- reduce split-K partials, add anchors, L2-normalize ------------
__global__ __launch_bounds__(1024) void finalK(
    const float* __restrict__ anchors, float* __restrict__ out)
{
    const int b = blockIdx.x, t = threadIdx.x;
    float* orow = out + (size_t)b * 8448;
    float ss = 0.0f;

    #pragma unroll
    for (int j = 0; j < 8; j++) {
        int e = t + j * 1024;
        int k = e >> 7, c = e & 127;
        float s2 = 0.0f, sps = 0.0f;
        #pragma unroll
        for (int sp = 0; sp < 8; sp++) {
            s2  += g_vpart[(((size_t)(b * 8 + sp) * 64) + k) * 128 + c];
            sps += g_pspart[(b * 8 + sp) * 64 + k];
        }
        float val = 2.0f * s2 - sps * anchors[k * 128 + c];
        orow[256 + e] = val;
        ss += val * val;
    }
    if (t < 256) { float tv = orow[t]; ss += tv * tv; }

    __shared__ float red[32];
    __shared__ float s_inv;
    float w = warpSum(ss);
    if ((t & 31) == 0) red[t >> 5] = w;
    __syncthreads();
    if (t < 32) {
        float v = red[t];
        v = warpSum(v);
        if (t == 0) s_inv = 1.0f / fmaxf(sqrtf(v), 1e-12f);
    }
    __syncthreads();
    const float inv = s_inv;
    for (int idx = t; idx < 8448; idx += 1024) orow[idx] *= inv;
}

// ---------------------------------------------------------------------------
extern "C" void kernel_launch(void* const* d_in, const int* in_sizes, int n_in,
                              void* d_out, int out_size)
{
    const float* x       = (const float*)d_in[0];
    const float* Wf      = (const float*)d_in[1];
    const float* bf      = (const float*)d_in[2];
    const float* Ws      = (const float*)d_in[3];
    const float* bs      = (const float*)d_in[4];
    const float* Wt      = (const float*)d_in[5];
    const float* bt      = (const float*)d_in[6];
    const float* anchors = (const float*)d_in[7];
    // d_in[8] = dust_bin: provably cancels out of the transport plan (constant
    // row shift absorbed by u), so it is not needed on-device.
    const float* sharp   = (const float*)d_in[9];
    float* out = (float*)d_out;

    gemmA<<<dim3(3, 8, 32), 256>>>(x, Wf, bf, Ws, bs, sharp);
    rowmaxK<<<dim3(2, 32), 1024>>>();
    expK<<<2048, 1024>>>();
    initC<<<32, 1024>>>();
    for (int it = 0; it < 5; it++) {
        sink_r<<<32, 1024>>>();
        sink_c<<<dim3(4, 32), 256>>>();
    }
    gemmC<<<dim3(8, 32), 256>>>();
    tK<<<32, 256>>>(x, Wt, bt, out);
    finalK<<<32, 1024>>>(anchors, out);
}

// round 4
// speedup vs baseline: 1.3139x; 1.3139x over previous
#include <cuda_runtime.h>
#include <cuda_fp16.h>
#include <math.h>
#include <stdint.h>

#define LOG2E_F 1.4426950408889634f

// ---------------- scratch (static device globals; no allocs) ----------------
__device__ float g_f[32 * 1024 * 128];       // f = fi@Wf + bf           16 MB
__device__ float g_K[32 * 64 * 1024];        // M' -> K~ (in place)       8 MB
__device__ float g_r[32 * 65];               // Sinkhorn row scalings
__device__ float g_c[32 * 1024];             // Sinkhorn col scalings
__device__ float g_vpart[32 * 8 * 64 * 128]; // split-K partials of p@f
__device__ float g_pspart[32 * 8 * 64];      // split-K partials of rowsum(p)
__device__ __half g_Bhi[192 * 768];          // (W^T * 256) hi, [n][k]
__device__ __half g_Blo[192 * 768];          // (W^T * 256) lo

// ------------------------------- helpers -------------------------------------
__device__ __forceinline__ float warpSum(float v) {
    #pragma unroll
    for (int o = 16; o > 0; o >>= 1) v += __shfl_xor_sync(0xffffffffu, v, o);
    return v;
}
__device__ __forceinline__ float warpMax(float v) {
    #pragma unroll
    for (int o = 16; o > 0; o >>= 1) v = fmaxf(v, __shfl_xor_sync(0xffffffffu, v, o));
    return v;
}
__device__ __forceinline__ float fast_exp2(float x) {
    float y;
    asm("ex2.approx.ftz.f32 %0, %1;" : "=f"(y) : "f"(x));
    return y;
}
__device__ __forceinline__ void mma16816(float* d, uint32_t a0, uint32_t a1,
                                         uint32_t a2, uint32_t a3,
                                         uint32_t b0, uint32_t b1) {
    asm volatile(
        "mma.sync.aligned.m16n8k16.row.col.f32.f16.f16.f32 "
        "{%0,%1,%2,%3}, {%4,%5,%6,%7}, {%8,%9}, {%0,%1,%2,%3};"
        : "+f"(d[0]), "+f"(d[1]), "+f"(d[2]), "+f"(d[3])
        : "r"(a0), "r"(a1), "r"(a2), "r"(a3), "r"(b0), "r"(b1));
}
__device__ __forceinline__ uint32_t pack_h2(__half a, __half b) {
    __half2 h = __halves2half2(a, b);
    return *(uint32_t*)&h;
}

// ------------------- prepB: (W^T * 256) -> fp16 hi/lo ------------------------
__global__ __launch_bounds__(256) void prepB(
    const float* __restrict__ Wf, const float* __restrict__ Ws)
{
    int i = blockIdx.x * 256 + threadIdx.x;     // 192*768
    int n = i / 768, k = i - n * 768;
    float v = (n < 128) ? Wf[(size_t)k * 128 + n] : Ws[(size_t)k * 64 + (n - 128)];
    v *= 256.0f;                                 // keep residual in fp16 normal range
    __half hi = __float2half_rn(v);
    float r = v - __half2float(hi);
    g_Bhi[i] = hi;
    g_Blo[i] = __float2half_rn(r);
}

// ---------------------------------------------------------------------------
// gemmA via mma.sync (fp16 hi/lo split, fp32 accum).
// Per CTA: M=128 rows (tokens), N=192 cols, K=768 in 12 chunks of 64.
// 8 warps: 4 row-groups x 2 col-groups; warp tile 32x96 (2 mfrag x 12 nfrag).
// smem stride: 72 halfs (144 B) per row -> conflict-free fragment loads.
// ---------------------------------------------------------------------------
#define SMA_HI 0
#define SMA_LO (128 * 144)
#define SMB_HI (2 * 128 * 144)
#define SMB_LO (2 * 128 * 144 + 192 * 144)
#define SM_TOTAL (2 * 128 * 144 + 2 * 192 * 144)   // 92160 B

__global__ __launch_bounds__(256) void gemmA_mma(
    const float* __restrict__ x, const float* __restrict__ bf,
    const float* __restrict__ bs, const float* __restrict__ sharp)
{
    extern __shared__ char sm[];
    const int tid = threadIdx.x, wid = tid >> 5, lane = tid & 31;
    const int b = blockIdx.y, nt = blockIdx.x;
    const int wr = wid & 3, wc = wid >> 2;
    const int g = lane >> 2, tig = lane & 3;

    const float* A = x + (size_t)b * 1025 * 768 + 768 + (size_t)nt * 128 * 768;

    float acc[2][12][4];
    #pragma unroll
    for (int mf = 0; mf < 2; mf++)
        #pragma unroll
        for (int nf = 0; nf < 12; nf++)
            #pragma unroll
            for (int q = 0; q < 4; q++) acc[mf][nf][q] = 0.0f;

    for (int ch = 0; ch < 12; ch++) {
        const int k0 = ch * 64;
        __syncthreads();
        // ---- A chunk: 128x64 fp32 -> fp16 hi/lo into smem ----
        #pragma unroll
        for (int i = 0; i < 8; i++) {
            int e = tid + i * 256;
            int row = e >> 4, c4 = (e & 15) * 4;
            float4 v = *(const float4*)(A + (size_t)row * 768 + k0 + c4);
            __half hx = __float2half_rn(v.x), hy = __float2half_rn(v.y);
            __half hz = __float2half_rn(v.z), hw = __float2half_rn(v.w);
            __half lx = __float2half_rn(v.x - __half2float(hx));
            __half ly = __float2half_rn(v.y - __half2float(hy));
            __half lz = __float2half_rn(v.z - __half2float(hz));
            __half lw = __float2half_rn(v.w - __half2float(hw));
            uint32_t off = row * 144 + c4 * 2;
            *(uint2*)(sm + SMA_HI + off) = make_uint2(pack_h2(hx, hy), pack_h2(hz, hw));
            *(uint2*)(sm + SMA_LO + off) = make_uint2(pack_h2(lx, ly), pack_h2(lz, lw));
        }
        // ---- B chunk: 192x64 halfs (hi+lo) from preconverted gmem ----
        #pragma unroll
        for (int i = 0; i < 6; i++) {
            int e = tid + i * 256;
            int n = e >> 3, u = e & 7;
            uint32_t off = n * 144 + u * 16;
            size_t src = (size_t)n * 768 + k0 + u * 8;
            *(uint4*)(sm + SMB_HI + off) = *(const uint4*)(g_Bhi + src);
            *(uint4*)(sm + SMB_LO + off) = *(const uint4*)(g_Blo + src);
        }
        __syncthreads();

        #pragma unroll
        for (int ks = 0; ks < 4; ks++) {
            const int kk = ks * 16;
            uint32_t ahi[2][4], alo[2][4];
            #pragma unroll
            for (int mf = 0; mf < 2; mf++) {
                int r0 = (wr * 32 + mf * 16 + g) * 144 + (kk + tig * 2) * 2;
                int r1 = r0 + 8 * 144;
                ahi[mf][0] = *(const uint32_t*)(sm + SMA_HI + r0);
                ahi[mf][1] = *(const uint32_t*)(sm + SMA_HI + r1);
                ahi[mf][2] = *(const uint32_t*)(sm + SMA_HI + r0 + 16);
                ahi[mf][3] = *(const uint32_t*)(sm + SMA_HI + r1 + 16);
                alo[mf][0] = *(const uint32_t*)(sm + SMA_LO + r0);
                alo[mf][1] = *(const uint32_t*)(sm + SMA_LO + r1);
                alo[mf][2] = *(const uint32_t*)(sm + SMA_LO + r0 + 16);
                alo[mf][3] = *(const uint32_t*)(sm + SMA_LO + r1 + 16);
            }
            #pragma unroll
            for (int nf = 0; nf < 12; nf++) {
                int nb = (wc * 96 + nf * 8 + g) * 144 + (kk + tig * 2) * 2;
                uint32_t bh0 = *(const uint32_t*)(sm + SMB_HI + nb);
                uint32_t bh1 = *(const uint32_t*)(sm + SMB_HI + nb + 16);
                uint32_t bl0 = *(const uint32_t*)(sm + SMB_LO + nb);
                uint32_t bl1 = *(const uint32_t*)(sm + SMB_LO + nb + 16);
                #pragma unroll
                for (int mf = 0; mf < 2; mf++) {
                    mma16816(acc[mf][nf], ahi[mf][0], ahi[mf][1], ahi[mf][2], ahi[mf][3], bh0, bh1);
                    mma16816(acc[mf][nf], ahi[mf][0], ahi[mf][1], ahi[mf][2], ahi[mf][3], bl0, bl1);
                    mma16816(acc[mf][nf], alo[mf][0], alo[mf][1], alo[mf][2], alo[mf][3], bh0, bh1);
                }
            }
        }
    }

    // ---------------------------- epilogue ----------------------------------
    const float inv256 = 1.0f / 256.0f;
    const float scl = sharp[0] * 10.0f * LOG2E_F;   // sharpness/REG * log2(e)
    #pragma unroll
    for (int mf = 0; mf < 2; mf++) {
        #pragma unroll
        for (int nf = 0; nf < 12; nf++) {
            int c = wc * 96 + nf * 8 + tig * 2;
            int r0 = nt * 128 + wr * 32 + mf * 16 + g;
            int r1 = r0 + 8;
            float d0 = acc[mf][nf][0], d1 = acc[mf][nf][1];
            float d2 = acc[mf][nf][2], d3 = acc[mf][nf][3];
            if (c < 128) {
                float b0 = __ldg(bf + c), b1 = __ldg(bf + c + 1);
                *(float2*)(g_f + ((size_t)(b * 1024 + r0)) * 128 + c) =
                    make_float2(fmaf(d0, inv256, b0), fmaf(d1, inv256, b1));
                *(float2*)(g_f + ((size_t)(b * 1024 + r1)) * 128 + c) =
                    make_float2(fmaf(d2, inv256, b0), fmaf(d3, inv256, b1));
            } else {
                int k = c - 128;
                float b0 = __ldg(bs + k), b1 = __ldg(bs + k + 1);
                float* K0 = g_K + ((size_t)(b * 64 + k)) * 1024;
                float* K1 = g_K + ((size_t)(b * 64 + k + 1)) * 1024;
                K0[r0] = fmaf(d0, inv256, b0) * scl;
                K1[r0] = fmaf(d1, inv256, b1) * scl;
                K0[r1] = fmaf(d2, inv256, b0) * scl;
                K1[r1] = fmaf(d3, inv256, b1) * scl;
            }
        }
    }
}

// ------------- expprep: rowmax + exp2 + rowsum -> initial r ------------------
__global__ __launch_bounds__(256) void expprep()
{
    const int row = blockIdx.x;              // b*64 + k
    float4* p = (float4*)(g_K + ((size_t)row << 10));
    const int t = threadIdx.x;
    float4 v = p[t];
    __shared__ float red[8];
    __shared__ float s_bm;
    float mx = fmaxf(fmaxf(v.x, v.y), fmaxf(v.z, v.w));
    mx = warpMax(mx);
    if ((t & 31) == 0) red[t >> 5] = mx;
    __syncthreads();
    if (t == 0) {
        float mm = red[0];
        #pragma unroll
        for (int i = 1; i < 8; i++) mm = fmaxf(mm, red[i]);
        s_bm = mm;
    }
    __syncthreads();
    const float m = s_bm;
    v.x = fast_exp2(v.x - m); v.y = fast_exp2(v.y - m);
    v.z = fast_exp2(v.z - m); v.w = fast_exp2(v.w - m);
    p[t] = v;
    float s = (v.x + v.y) + (v.z + v.w);
    s = warpSum(s);
    if ((t & 31) == 0) red[t >> 5] = s;
    __syncthreads();
    if (t == 0) {
        float tot = 0.0f;
        #pragma unroll
        for (int i = 0; i < 8; i++) tot += red[i];
        g_r[(row >> 6) * 65 + (row & 63)] = (1.0f / 65.0f) / tot;
        if ((row & 63) == 0) g_r[(row >> 6) * 65 + 64] = (1.0f / 65.0f) / 1024.0f;
    }
}

// ------------- fused Sinkhorn: 5 c-updates + 4 r-updates, one launch ---------
__global__ __launch_bounds__(1024) void sinkhorn()
{
    const int b = blockIdx.x;
    const int t = threadIdx.x, w = t >> 5, l = t & 31;
    __shared__ float cs[1024];
    __shared__ float rs[72];
    __shared__ float red[32];
    if (t < 65) rs[t] = g_r[b * 65 + t];
    __syncthreads();
    const float* Kb = g_K + ((size_t)b << 16);

    #pragma unroll 1
    for (int it = 0; it < 5; it++) {
        // c-update (thread = column t)
        float acc = rs[64];
        const float* col = Kb + t;
        #pragma unroll 8
        for (int k = 0; k < 64; k++) acc = fmaf(col[(size_t)k << 10], rs[k], acc);
        float cv = (1.0f / 1024.0f) / acc;
        cs[t] = cv;
        float sw = warpSum(cv);
        if (l == 0) red[w] = sw;
        __syncthreads();
        if (it < 4) {
            if (t == 0) {
                float s = 0.0f;
                #pragma unroll
                for (int i = 0; i < 32; i++) s += red[i];
                rs[64] = (1.0f / 65.0f) / s;
            }
            // r-update (warp w -> rows w, w+32)
            #pragma unroll
            for (int rr = 0; rr < 2; rr++) {
                int k = w + rr * 32;
                const float* row = Kb + ((size_t)k << 10);
                float d = 0.0f;
                #pragma unroll 8
                for (int n = l; n < 1024; n += 32) d = fmaf(row[n], cs[n], d);
                d = warpSum(d);
                if (l == 0) rs[k] = (1.0f / 65.0f) / d;
            }
            __syncthreads();
        }
    }
    g_c[b * 1024 + t] = cs[t];
    if (t < 65) g_r[b * 65 + t] = rs[t];
}

// ---------------------------------------------------------------------------
// GEMM C: partial (64x128) = p_slice @ f_slice, p materialized as K~ * r * c.
// ---------------------------------------------------------------------------
__global__ __launch_bounds__(256) void gemmC()
{
    const int b = blockIdx.y, sp = blockIdx.x;
    const int tid = threadIdx.x;
    const int tx = tid & 15, ty = tid >> 4;
    __shared__ float ps[64][33];
    __shared__ float fs[32][128];

    const int n0 = sp * 128;
    float acc[4][8];
    #pragma unroll
    for (int i = 0; i < 4; i++)
        #pragma unroll
        for (int j = 0; j < 8; j++) acc[i][j] = 0.0f;
    float psum = 0.0f;

    for (int c0 = 0; c0 < 128; c0 += 32) {
        __syncthreads();
        #pragma unroll
        for (int j = 0; j < 2; j++) {
            int idx4 = tid + j * 256;
            int k = idx4 >> 3;
            int nn4 = (idx4 & 7) * 4;
            float4 kv = *(const float4*)(g_K + ((size_t)(b * 64 + k)) * 1024 + n0 + c0 + nn4);
            float4 cv = *(const float4*)(g_c + b * 1024 + n0 + c0 + nn4);
            float rv = __ldg(&g_r[b * 65 + k]);
            ps[k][nn4 + 0] = kv.x * cv.x * rv;
            ps[k][nn4 + 1] = kv.y * cv.y * rv;
            ps[k][nn4 + 2] = kv.z * cv.z * rv;
            ps[k][nn4 + 3] = kv.w * cv.w * rv;
        }
        #pragma unroll
        for (int j = 0; j < 4; j++) {
            int idx4 = tid + j * 256;
            int nn = idx4 >> 5;
            int c4 = (idx4 & 31) * 4;
            *(float4*)&fs[nn][c4] =
                *(const float4*)(g_f + ((size_t)(b * 1024 + n0 + c0 + nn)) * 128 + c4);
        }
        __syncthreads();

        #pragma unroll
        for (int nn = 0; nn < 32; nn++) {
            float a4[4];
            #pragma unroll
            for (int i = 0; i < 4; i++) a4[i] = ps[ty * 4 + i][nn];
            float4 b0 = *(const float4*)&fs[nn][tx * 8];
            float4 b1 = *(const float4*)&fs[nn][tx * 8 + 4];
            float b8[8] = {b0.x, b0.y, b0.z, b0.w, b1.x, b1.y, b1.z, b1.w};
            #pragma unroll
            for (int i = 0; i < 4; i++)
                #pragma unroll
                for (int j = 0; j < 8; j++)
                    acc[i][j] = fmaf(a4[i], b8[j], acc[i][j]);
        }

        if (tid < 64) {
            float s = 0.0f;
            #pragma unroll
            for (int nn = 0; nn < 32; nn++) s += ps[tid][nn];
            psum += s;
        }
    }

    #pragma unroll
    for (int i = 0; i < 4; i++) {
        float* dst = g_vpart + (((size_t)(b * 8 + sp) * 64) + ty * 4 + i) * 128 + tx * 8;
        *(float4*)(dst)     = make_float4(acc[i][0], acc[i][1], acc[i][2], acc[i][3]);
        *(float4*)(dst + 4) = make_float4(acc[i][4], acc[i][5], acc[i][6], acc[i][7]);
    }
    if (tid < 64) g_pspart[(b * 8 + sp) * 64 + tid] = psum;
}

// --------------------------- t = x[:,0] @ Wt + bt ----------------------------
__global__ __launch_bounds__(256) void tK(
    const float* __restrict__ x, const float* __restrict__ Wt,
    const float* __restrict__ bt, float* __restrict__ out)
{
    const int b = blockIdx.x;
    const int c = threadIdx.x;
    __shared__ float xs[768];
    for (int i = c; i < 768; i += 256) xs[i] = x[(size_t)b * 1025 * 768 + i];
    __syncthreads();
    float acc = bt[c];
    #pragma unroll 8
    for (int d = 0; d < 768; d++) acc = fmaf(xs[d], Wt[(size_t)d * 256 + c], acc);
    out[(size_t)b * 8448 + c] = acc;
}

// ------------- reduce split-K partials, add anchors, L2-normalize ------------
__global__ __launch_bounds__(1024) void finalK(
    const float* __restrict__ anchors, float* __restrict__ out)
{
    const int b = blockIdx.x, t = threadIdx.x;
    float* orow = out + (size_t)b * 8448;
    float ss = 0.0f;

    #pragma unroll
    for (int j = 0; j < 8; j++) {
        int e = t + j * 1024;
        int k = e >> 7, c = e & 127;
        float s2 = 0.0f, sps = 0.0f;
        #pragma unroll
        for (int sp = 0; sp < 8; sp++) {
            s2  += g_vpart[(((size_t)(b * 8 + sp) * 64) + k) * 128 + c];
            sps += g_pspart[(b * 8 + sp) * 64 + k];
        }
        float val = 2.0f * s2 - sps * anchors[k * 128 + c];
        orow[256 + e] = val;
        ss += val * val;
    }
    if (t < 256) { float tv = orow[t]; ss += tv * tv; }

    __shared__ float red[32];
    __shared__ float s_inv;
    float w = warpSum(ss);
    if ((t & 31) == 0) red[t >> 5] = w;
    __syncthreads();
    if (t < 32) {
        float v = red[t];
        v = warpSum(v);
        if (t == 0) s_inv = 1.0f / fmaxf(sqrtf(v), 1e-12f);
    }
    __syncthreads();
    const float inv = s_inv;
    for (int idx = t; idx < 8448; idx += 1024) orow[idx] *= inv;
}

// ---------------------------------------------------------------------------
extern "C" void kernel_launch(void* const* d_in, const int* in_sizes, int n_in,
                              void* d_out, int out_size)
{
    const float* x       = (const float*)d_in[0];
    const float* Wf      = (const float*)d_in[1];
    const float* bf      = (const float*)d_in[2];
    const float* Ws      = (const float*)d_in[3];
    const float* bs      = (const float*)d_in[4];
    const float* Wt      = (const float*)d_in[5];
    const float* bt      = (const float*)d_in[6];
    const float* anchors = (const float*)d_in[7];
    // d_in[8] = dust_bin: constant row shift, cancels in the transport plan.
    const float* sharp   = (const float*)d_in[9];
    float* out = (float*)d_out;

    static int smem_set = 0;
    if (!smem_set) {
        cudaFuncSetAttribute(gemmA_mma, cudaFuncAttributeMaxDynamicSharedMemorySize, SM_TOTAL);
        smem_set = 1;
    }

    prepB<<<576, 256>>>(Wf, Ws);
    gemmA_mma<<<dim3(8, 32), 256, SM_TOTAL>>>(x, bf, bs, sharp);
    expprep<<<2048, 256>>>();
    sinkhorn<<<32, 1024>>>();
    gemmC<<<dim3(8, 32), 256>>>();
    tK<<<32, 256>>>(x, Wt, bt, out);
    finalK<<<32, 1024>>>(anchors, out);
}

// round 5
// speedup vs baseline: 1.7329x; 1.3188x over previous
#include <cuda_runtime.h>
#include <cuda_fp16.h>
#include <math.h>
#include <stdint.h>

#define LOG2E_F 1.4426950408889634f

// ---------------- scratch (static device globals; no allocs) ----------------
__device__ float g_f[32 * 1024 * 128];       // f = fi@Wf + bf           16 MB
__device__ float g_K[32 * 64 * 1024];        // M' -> K~ (in place)       8 MB
__device__ float g_r[32 * 65];               // Sinkhorn row scalings
__device__ float g_c[32 * 1024];             // Sinkhorn col scalings
__device__ float g_vpart[32 * 8 * 64 * 128]; // split-K partials of p@f
__device__ float g_pspart[32 * 8 * 64];      // split-K partials of rowsum(p)
__device__ __half g_Bhi[192 * 768];          // (W^T * 256) hi, [n][k]
__device__ __half g_Blo[192 * 768];          // (W^T * 256) lo

// ------------------------------- helpers -------------------------------------
__device__ __forceinline__ float warpSum(float v) {
    #pragma unroll
    for (int o = 16; o > 0; o >>= 1) v += __shfl_xor_sync(0xffffffffu, v, o);
    return v;
}
__device__ __forceinline__ float warpMax(float v) {
    #pragma unroll
    for (int o = 16; o > 0; o >>= 1) v = fmaxf(v, __shfl_xor_sync(0xffffffffu, v, o));
    return v;
}
// exp2 on the FMA pipe (x <= 0 here). deg-5 Taylor on [-0.5,0.5], rel err ~2e-6.
__device__ __forceinline__ float exp2_fma(float x) {
    x = fmaxf(x, -125.0f);
    int   ni = __float2int_rn(x);
    float f  = x - (float)ni;
    float p  = 1.3333558e-3f;                 // (ln2)^5/120
    p = fmaf(p, f, 9.6181290e-3f);            // (ln2)^4/24
    p = fmaf(p, f, 5.5504109e-2f);            // (ln2)^3/6
    p = fmaf(p, f, 2.4022651e-1f);            // (ln2)^2/2
    p = fmaf(p, f, 6.9314718e-1f);            // ln2
    p = fmaf(p, f, 1.0f);
    return p * __int_as_float((ni + 127) << 23);
}
__device__ __forceinline__ void mma16816(float* d, uint32_t a0, uint32_t a1,
                                         uint32_t a2, uint32_t a3,
                                         uint32_t b0, uint32_t b1) {
    asm volatile(
        "mma.sync.aligned.m16n8k16.row.col.f32.f16.f16.f32 "
        "{%0,%1,%2,%3}, {%4,%5,%6,%7}, {%8,%9}, {%0,%1,%2,%3};"
        : "+f"(d[0]), "+f"(d[1]), "+f"(d[2]), "+f"(d[3])
        : "r"(a0), "r"(a1), "r"(a2), "r"(a3), "r"(b0), "r"(b1));
}
__device__ __forceinline__ uint32_t pack_h2(__half a, __half b) {
    __half2 h = __halves2half2(a, b);
    return *(uint32_t*)&h;
}
__device__ __forceinline__ uint32_t smem_u32(const void* p) {
    uint32_t a;
    asm("{ .reg .u64 t; cvta.to.shared.u64 t, %1; cvt.u32.u64 %0, t; }" : "=r"(a) : "l"(p));
    return a;
}
__device__ __forceinline__ void cpasync16(uint32_t dst, const void* src) {
    asm volatile("cp.async.cg.shared.global [%0], [%1], 16;" :: "r"(dst), "l"(src));
}
#define CP_COMMIT() asm volatile("cp.async.commit_group;" ::: "memory")
#define CP_WAIT0()  asm volatile("cp.async.wait_group 0;" ::: "memory")
#define CP_WAIT1()  asm volatile("cp.async.wait_group 1;" ::: "memory")

// ------------------- prepB: (W^T * 256) -> fp16 hi/lo ------------------------
__global__ __launch_bounds__(256) void prepB(
    const float* __restrict__ Wf, const float* __restrict__ Ws)
{
    int i = blockIdx.x * 256 + threadIdx.x;     // 192*768
    int n = i / 768, k = i - n * 768;
    float v = (n < 128) ? Wf[(size_t)k * 128 + n] : Ws[(size_t)k * 64 + (n - 128)];
    v *= 256.0f;                                 // keep residual in fp16 normal range
    __half hi = __float2half_rn(v);
    float r = v - __half2float(hi);
    g_Bhi[i] = hi;
    g_Blo[i] = __float2half_rn(r);
}

// ---------------------------------------------------------------------------
// gemmA via mma.sync, software-pipelined.
// f cols (0..127): 2-term split (Ahi*Bhi + Ahi*Blo); s cols (128..191): 3-term.
// A chunk register-prefetched (LDG overlaps prior MMA); B double-buffered cp.async.
// ---------------------------------------------------------------------------
#define SMA_HI 0
#define SMA_LO (128 * 144)
#define SMB(buf) (2 * 128 * 144 + (buf) * (2 * 192 * 144))
#define SMB_LO_OFF (192 * 144)
#define SM_TOTAL (2 * 128 * 144 + 2 * 2 * 192 * 144)   // 147456 B

__global__ __launch_bounds__(256) void gemmA_mma(
    const float* __restrict__ x, const float* __restrict__ bf,
    const float* __restrict__ bs, const float* __restrict__ sharp)
{
    extern __shared__ char sm[];
    const uint32_t smu = smem_u32(sm);
    const int tid = threadIdx.x, wid = tid >> 5, lane = tid & 31;
    const int b = blockIdx.y, nt = blockIdx.x;
    const int wr = wid & 3, wc = wid >> 2;
    const int g = lane >> 2, tig = lane & 3;
    const bool haveLo = (wc == 1);       // only wc=1 warps touch s-cols (3rd term)

    const float* A = x + (size_t)b * 1025 * 768 + 768 + (size_t)nt * 128 * 768;
    const int am = tid >> 1, akb = (tid & 1) * 32;
    const float* aptr = A + (size_t)am * 768 + akb;

    float acc[2][12][4];
    #pragma unroll
    for (int mf = 0; mf < 2; mf++)
        #pragma unroll
        for (int nf = 0; nf < 12; nf++)
            #pragma unroll
            for (int q = 0; q < 4; q++) acc[mf][nf][q] = 0.0f;

    float4 aPre[8];
    // ---- preload chunk 0 ----
    #pragma unroll
    for (int i = 0; i < 8; i++) aPre[i] = *(const float4*)(aptr + i * 4);
    #pragma unroll
    for (int j = 0; j < 6; j++) {
        int e = tid + j * 256;
        int n = e >> 3, u = e & 7;
        uint32_t doff = (uint32_t)(n * 144 + u * 16);
        cpasync16(smu + SMB(0) + doff, g_Bhi + (size_t)n * 768 + u * 8);
        cpasync16(smu + SMB(0) + SMB_LO_OFF + doff, g_Blo + (size_t)n * 768 + u * 8);
    }
    CP_COMMIT();

    #pragma unroll 1
    for (int ch = 0; ch < 12; ch++) {
        const int buf = ch & 1;
        // ---- convert prefetched A regs -> smem hi/lo ----
        #pragma unroll
        for (int i = 0; i < 8; i++) {
            float4 v = aPre[i];
            __half hx = __float2half_rn(v.x), hy = __float2half_rn(v.y);
            __half hz = __float2half_rn(v.z), hw = __float2half_rn(v.w);
            __half lx = __float2half_rn(v.x - __half2float(hx));
            __half ly = __float2half_rn(v.y - __half2float(hy));
            __half lz = __float2half_rn(v.z - __half2float(hz));
            __half lw = __float2half_rn(v.w - __half2float(hw));
            uint32_t off = am * 144 + (akb + i * 4) * 2;
            *(uint2*)(sm + SMA_HI + off) = make_uint2(pack_h2(hx, hy), pack_h2(hz, hw));
            *(uint2*)(sm + SMA_LO + off) = make_uint2(pack_h2(lx, ly), pack_h2(lz, lw));
        }
        // ---- prefetch chunk ch+1 ----
        if (ch < 11) {
            const int k1 = (ch + 1) * 64;
            #pragma unroll
            for (int i = 0; i < 8; i++) aPre[i] = *(const float4*)(aptr + k1 + i * 4);
            #pragma unroll
            for (int j = 0; j < 6; j++) {
                int e = tid + j * 256;
                int n = e >> 3, u = e & 7;
                uint32_t doff = (uint32_t)(n * 144 + u * 16);
                cpasync16(smu + SMB(buf ^ 1) + doff, g_Bhi + (size_t)n * 768 + k1 + u * 8);
                cpasync16(smu + SMB(buf ^ 1) + SMB_LO_OFF + doff, g_Blo + (size_t)n * 768 + k1 + u * 8);
            }
            CP_COMMIT();
            CP_WAIT1();
        } else {
            CP_WAIT0();
        }
        __syncthreads();

        const char* BH = sm + SMB(buf);
        const char* BL = BH + SMB_LO_OFF;
        #pragma unroll
        for (int ks = 0; ks < 4; ks++) {
            const int kk = ks * 16;
            uint32_t ahi[2][4], alo[2][4];
            #pragma unroll
            for (int mf = 0; mf < 2; mf++) {
                int r0 = (wr * 32 + mf * 16 + g) * 144 + (kk + tig * 2) * 2;
                int r1 = r0 + 8 * 144;
                ahi[mf][0] = *(const uint32_t*)(sm + SMA_HI + r0);
                ahi[mf][1] = *(const uint32_t*)(sm + SMA_HI + r1);
                ahi[mf][2] = *(const uint32_t*)(sm + SMA_HI + r0 + 16);
                ahi[mf][3] = *(const uint32_t*)(sm + SMA_HI + r1 + 16);
                if (haveLo) {
                    alo[mf][0] = *(const uint32_t*)(sm + SMA_LO + r0);
                    alo[mf][1] = *(const uint32_t*)(sm + SMA_LO + r1);
                    alo[mf][2] = *(const uint32_t*)(sm + SMA_LO + r0 + 16);
                    alo[mf][3] = *(const uint32_t*)(sm + SMA_LO + r1 + 16);
                }
            }
            #pragma unroll
            for (int nf = 0; nf < 12; nf++) {
                int nb = (wc * 96 + nf * 8 + g) * 144 + (kk + tig * 2) * 2;
                uint32_t bh0 = *(const uint32_t*)(BH + nb);
                uint32_t bh1 = *(const uint32_t*)(BH + nb + 16);
                uint32_t bl0 = *(const uint32_t*)(BL + nb);
                uint32_t bl1 = *(const uint32_t*)(BL + nb + 16);
                #pragma unroll
                for (int mf = 0; mf < 2; mf++) {
                    mma16816(acc[mf][nf], ahi[mf][0], ahi[mf][1], ahi[mf][2], ahi[mf][3], bh0, bh1);
                    mma16816(acc[mf][nf], ahi[mf][0], ahi[mf][1], ahi[mf][2], ahi[mf][3], bl0, bl1);
                    if (haveLo && nf >= 4)   // s-cols only: 3rd term
                        mma16816(acc[mf][nf], alo[mf][0], alo[mf][1], alo[mf][2], alo[mf][3], bh0, bh1);
                }
            }
        }
        __syncthreads();
    }

    // ---------------------------- epilogue ----------------------------------
    const float inv256 = 1.0f / 256.0f;
    const float scl = sharp[0] * 10.0f * LOG2E_F;   // sharpness/REG * log2(e)
    #pragma unroll
    for (int mf = 0; mf < 2; mf++) {
        #pragma unroll
        for (int nf = 0; nf < 12; nf++) {
            int c = wc * 96 + nf * 8 + tig * 2;
            int r0 = nt * 128 + wr * 32 + mf * 16 + g;
            int r1 = r0 + 8;
            float d0 = acc[mf][nf][0], d1 = acc[mf][nf][1];
            float d2 = acc[mf][nf][2], d3 = acc[mf][nf][3];
            if (c < 128) {
                float b0 = __ldg(bf + c), b1 = __ldg(bf + c + 1);
                *(float2*)(g_f + ((size_t)(b * 1024 + r0)) * 128 + c) =
                    make_float2(fmaf(d0, inv256, b0), fmaf(d1, inv256, b1));
                *(float2*)(g_f + ((size_t)(b * 1024 + r1)) * 128 + c) =
                    make_float2(fmaf(d2, inv256, b0), fmaf(d3, inv256, b1));
            } else {
                int k = c - 128;
                float b0 = __ldg(bs + k), b1 = __ldg(bs + k + 1);
                float* K0 = g_K + ((size_t)(b * 64 + k)) * 1024;
                float* K1 = g_K + ((size_t)(b * 64 + k + 1)) * 1024;
                K0[r0] = fmaf(d0, inv256, b0) * scl;
                K1[r0] = fmaf(d1, inv256, b1) * scl;
                K0[r1] = fmaf(d2, inv256, b0) * scl;
                K1[r1] = fmaf(d3, inv256, b1) * scl;
            }
        }
    }
}

// ------------- expprep: rowmax + exp2 + rowsum -> initial r ------------------
__global__ __launch_bounds__(256) void expprep()
{
    const int row = blockIdx.x;              // b*64 + k
    float4* p = (float4*)(g_K + ((size_t)row << 10));
    const int t = threadIdx.x;
    float4 v = p[t];
    __shared__ float red[8];
    __shared__ float s_bm;
    float mx = fmaxf(fmaxf(v.x, v.y), fmaxf(v.z, v.w));
    mx = warpMax(mx);
    if ((t & 31) == 0) red[t >> 5] = mx;
    __syncthreads();
    if (t == 0) {
        float mm = red[0];
        #pragma unroll
        for (int i = 1; i < 8; i++) mm = fmaxf(mm, red[i]);
        s_bm = mm;
    }
    __syncthreads();
    const float m = s_bm;
    v.x = exp2_fma(v.x - m); v.y = exp2_fma(v.y - m);
    v.z = exp2_fma(v.z - m); v.w = exp2_fma(v.w - m);
    p[t] = v;
    float s = (v.x + v.y) + (v.z + v.w);
    s = warpSum(s);
    if ((t & 31) == 0) red[t >> 5] = s;
    __syncthreads();
    if (t == 0) {
        float tot = 0.0f;
        #pragma unroll
        for (int i = 0; i < 8; i++) tot += red[i];
        g_r[(row >> 6) * 65 + (row & 63)] = (1.0f / 65.0f) / tot;
        if ((row & 63) == 0) g_r[(row >> 6) * 65 + 64] = (1.0f / 65.0f) / 1024.0f;
    }
}

// ------------- fused Sinkhorn: 5 c-updates + 4 r-updates, one launch ---------
__global__ __launch_bounds__(1024) void sinkhorn()
{
    const int b = blockIdx.x;
    const int t = threadIdx.x, w = t >> 5, l = t & 31;
    __shared__ float cs[1024];
    __shared__ float rs[72];
    __shared__ float red[32];
    if (t < 65) rs[t] = g_r[b * 65 + t];
    __syncthreads();
    const float* Kb = g_K + ((size_t)b << 16);

    #pragma unroll 1
    for (int it = 0; it < 5; it++) {
        // c-update (thread = column t), 4 independent chains for MLP
        const float* col = Kb + t;
        float a0 = rs[64], a1 = 0.0f, a2 = 0.0f, a3 = 0.0f;
        #pragma unroll
        for (int k = 0; k < 64; k += 4) {
            a0 = fmaf(col[(size_t)(k + 0) << 10], rs[k + 0], a0);
            a1 = fmaf(col[(size_t)(k + 1) << 10], rs[k + 1], a1);
            a2 = fmaf(col[(size_t)(k + 2) << 10], rs[k + 2], a2);
            a3 = fmaf(col[(size_t)(k + 3) << 10], rs[k + 3], a3);
        }
        float cv = (1.0f / 1024.0f) / ((a0 + a1) + (a2 + a3));
        cs[t] = cv;
        float sw = warpSum(cv);
        if (l == 0) red[w] = sw;
        __syncthreads();
        if (it < 4) {
            if (t == 0) {
                float s = 0.0f;
                #pragma unroll
                for (int i = 0; i < 32; i++) s += red[i];
                rs[64] = (1.0f / 65.0f) / s;
            }
            // r-update (warp w -> rows w, w+32), 4 chains
            #pragma unroll
            for (int rr = 0; rr < 2; rr++) {
                int k = w + rr * 32;
                const float* row = Kb + ((size_t)k << 10);
                float d0 = 0.0f, d1 = 0.0f, d2 = 0.0f, d3 = 0.0f;
                #pragma unroll
                for (int n0 = 0; n0 < 1024; n0 += 128) {
                    d0 = fmaf(row[n0 + l],       cs[n0 + l],       d0);
                    d1 = fmaf(row[n0 + l + 32],  cs[n0 + l + 32],  d1);
                    d2 = fmaf(row[n0 + l + 64],  cs[n0 + l + 64],  d2);
                    d3 = fmaf(row[n0 + l + 96],  cs[n0 + l + 96],  d3);
                }
                float d = warpSum((d0 + d1) + (d2 + d3));
                if (l == 0) rs[k] = (1.0f / 65.0f) / d;
            }
            __syncthreads();
        }
    }
    g_c[b * 1024 + t] = cs[t];
    if (t < 65) g_r[b * 65 + t] = rs[t];
}

// ---------------------------------------------------------------------------
// GEMM C: partial (64x128) = p_slice @ f_slice, p materialized as K~ * r * c.
// ---------------------------------------------------------------------------
__global__ __launch_bounds__(256) void gemmC()
{
    const int b = blockIdx.y, sp = blockIdx.x;
    const int tid = threadIdx.x;
    const int tx = tid & 15, ty = tid >> 4;
    __shared__ float ps[64][33];
    __shared__ float fs[32][128];

    const int n0 = sp * 128;
    float acc[4][8];
    #pragma unroll
    for (int i = 0; i < 4; i++)
        #pragma unroll
        for (int j = 0; j < 8; j++) acc[i][j] = 0.0f;
    float psum = 0.0f;

    for (int c0 = 0; c0 < 128; c0 += 32) {
        __syncthreads();
        #pragma unroll
        for (int j = 0; j < 2; j++) {
            int idx4 = tid + j * 256;
            int k = idx4 >> 3;
            int nn4 = (idx4 & 7) * 4;
            float4 kv = *(const float4*)(g_K + ((size_t)(b * 64 + k)) * 1024 + n0 + c0 + nn4);
            float4 cv = *(const float4*)(g_c + b * 1024 + n0 + c0 + nn4);
            float rv = __ldg(&g_r[b * 65 + k]);
            ps[k][nn4 + 0] = kv.x * cv.x * rv;
            ps[k][nn4 + 1] = kv.y * cv.y * rv;
            ps[k][nn4 + 2] = kv.z * cv.z * rv;
            ps[k][nn4 + 3] = kv.w * cv.w * rv;
        }
        #pragma unroll
        for (int j = 0; j < 4; j++) {
            int idx4 = tid + j * 256;
            int nn = idx4 >> 5;
            int c4 = (idx4 & 31) * 4;
            *(float4*)&fs[nn][c4] =
                *(const float4*)(g_f + ((size_t)(b * 1024 + n0 + c0 + nn)) * 128 + c4);
        }
        __syncthreads();

        #pragma unroll
        for (int nn = 0; nn < 32; nn++) {
            float a4[4];
            #pragma unroll
            for (int i = 0; i < 4; i++) a4[i] = ps[ty * 4 + i][nn];
            float4 b0 = *(const float4*)&fs[nn][tx * 8];
            float4 b1 = *(const float4*)&fs[nn][tx * 8 + 4];
            float b8[8] = {b0.x, b0.y, b0.z, b0.w, b1.x, b1.y, b1.z, b1.w};
            #pragma unroll
            for (int i = 0; i < 4; i++)
                #pragma unroll
                for (int j = 0; j < 8; j++)
                    acc[i][j] = fmaf(a4[i], b8[j], acc[i][j]);
        }

        if (tid < 64) {
            float s = 0.0f;
            #pragma unroll
            for (int nn = 0; nn < 32; nn++) s += ps[tid][nn];
            psum += s;
        }
    }

    #pragma unroll
    for (int i = 0; i < 4; i++) {
        float* dst = g_vpart + (((size_t)(b * 8 + sp) * 64) + ty * 4 + i) * 128 + tx * 8;
        *(float4*)(dst)     = make_float4(acc[i][0], acc[i][1], acc[i][2], acc[i][3]);
        *(float4*)(dst + 4) = make_float4(acc[i][4], acc[i][5], acc[i][6], acc[i][7]);
    }
    if (tid < 64) g_pspart[(b * 8 + sp) * 64 + tid] = psum;
}

// --- finalK: t = x0@Wt + bt fused with split-K reduction + L2 normalize -----
__global__ __launch_bounds__(1024) void finalK(
    const float* __restrict__ x, const float* __restrict__ Wt,
    const float* __restrict__ bt, const float* __restrict__ anchors,
    float* __restrict__ out)
{
    const int b = blockIdx.x, t = threadIdx.x;
    float* orow = out + (size_t)b * 8448;
    __shared__ float xs[768];
    if (t < 768) xs[t] = x[(size_t)b * 1025 * 768 + t];
    __syncthreads();

    float ss = 0.0f;
    // v part: reduce split-K partials
    #pragma unroll
    for (int j = 0; j < 8; j++) {
        int e = t + j * 1024;
        int k = e >> 7, c = e & 127;
        float s2 = 0.0f, sps = 0.0f;
        #pragma unroll
        for (int sp = 0; sp < 8; sp++) {
            s2  += g_vpart[(((size_t)(b * 8 + sp) * 64) + k) * 128 + c];
            sps += g_pspart[(b * 8 + sp) * 64 + k];
        }
        float val = 2.0f * s2 - sps * anchors[k * 128 + c];
        orow[256 + e] = val;
        ss += val * val;
    }
    // t part (threads 0..255)
    if (t < 256) {
        float tv = bt[t];
        #pragma unroll 8
        for (int d = 0; d < 768; d++) tv = fmaf(xs[d], Wt[(size_t)d * 256 + t], tv);
        orow[t] = tv;
        ss += tv * tv;
    }

    __shared__ float red[32];
    __shared__ float s_inv;
    float w = warpSum(ss);
    if ((t & 31) == 0) red[t >> 5] = w;
    __syncthreads();
    if (t < 32) {
        float v = red[t];
        v = warpSum(v);
        if (t == 0) s_inv = 1.0f / fmaxf(sqrtf(v), 1e-12f);
    }
    __syncthreads();
    const float inv = s_inv;
    for (int idx = t; idx < 8448; idx += 1024) orow[idx] *= inv;
}

// ---------------------------------------------------------------------------
extern "C" void kernel_launch(void* const* d_in, const int* in_sizes, int n_in,
                              void* d_out, int out_size)
{
    const float* x       = (const float*)d_in[0];
    const float* Wf      = (const float*)d_in[1];
    const float* bf      = (const float*)d_in[2];
    const float* Ws      = (const float*)d_in[3];
    const float* bs      = (const float*)d_in[4];
    const float* Wt      = (const float*)d_in[5];
    const float* bt      = (const float*)d_in[6];
    const float* anchors = (const float*)d_in[7];
    // d_in[8] = dust_bin: constant row shift, cancels in the transport plan.
    const float* sharp   = (const float*)d_in[9];
    float* out = (float*)d_out;

    static int smem_set = 0;
    if (!smem_set) {
        cudaFuncSetAttribute(gemmA_mma, cudaFuncAttributeMaxDynamicSharedMemorySize, SM_TOTAL);
        smem_set = 1;
    }

    prepB<<<576, 256>>>(Wf, Ws);
    gemmA_mma<<<dim3(8, 32), 256, SM_TOTAL>>>(x, bf, bs, sharp);
    expprep<<<2048, 256>>>();
    sinkhorn<<<32, 1024>>>();
    gemmC<<<dim3(8, 32), 256>>>();
    finalK<<<32, 1024>>>(x, Wt, bt, anchors, out);
}

// round 6
// speedup vs baseline: 1.8452x; 1.0648x over previous
#include <cuda_runtime.h>
#include <cuda_fp16.h>
#include <math.h>
#include <stdint.h>

#define LOG2E_F 1.4426950408889634f

// ---------------- scratch (static device globals; no allocs) ----------------
__device__ float g_f[32 * 1024 * 128];       // f = fi@Wf + bf           16 MB
__device__ float g_K[32 * 64 * 1024];        // M' -> K~ (in place)       8 MB
__device__ float g_r[32 * 65];               // Sinkhorn row scalings
__device__ float g_c[32 * 1024];             // Sinkhorn col scalings
__device__ float g_vpart[32 * 8 * 64 * 128]; // split-K partials of p@f
__device__ float g_pspart[32 * 8 * 64];      // split-K partials of rowsum(p)
__device__ __half g_Bhi[192 * 768];          // (W^T * 256) hi, [n][k]
__device__ __half g_Blo[192 * 768];          // (W^T * 256) lo

// ------------------------------- helpers -------------------------------------
__device__ __forceinline__ float warpSum(float v) {
    #pragma unroll
    for (int o = 16; o > 0; o >>= 1) v += __shfl_xor_sync(0xffffffffu, v, o);
    return v;
}
__device__ __forceinline__ float warpMax(float v) {
    #pragma unroll
    for (int o = 16; o > 0; o >>= 1) v = fmaxf(v, __shfl_xor_sync(0xffffffffu, v, o));
    return v;
}
// exp2 on the FMA pipe (x <= 0 here). deg-5 Taylor on [-0.5,0.5], rel err ~2e-6.
__device__ __forceinline__ float exp2_fma(float x) {
    x = fmaxf(x, -125.0f);
    int   ni = __float2int_rn(x);
    float f  = x - (float)ni;
    float p  = 1.3333558e-3f;
    p = fmaf(p, f, 9.6181290e-3f);
    p = fmaf(p, f, 5.5504109e-2f);
    p = fmaf(p, f, 2.4022651e-1f);
    p = fmaf(p, f, 6.9314718e-1f);
    p = fmaf(p, f, 1.0f);
    return p * __int_as_float((ni + 127) << 23);
}
__device__ __forceinline__ void mma16816(float* d, uint32_t a0, uint32_t a1,
                                         uint32_t a2, uint32_t a3,
                                         uint32_t b0, uint32_t b1) {
    asm volatile(
        "mma.sync.aligned.m16n8k16.row.col.f32.f16.f16.f32 "
        "{%0,%1,%2,%3}, {%4,%5,%6,%7}, {%8,%9}, {%0,%1,%2,%3};"
        : "+f"(d[0]), "+f"(d[1]), "+f"(d[2]), "+f"(d[3])
        : "r"(a0), "r"(a1), "r"(a2), "r"(a3), "r"(b0), "r"(b1));
}
__device__ __forceinline__ uint32_t pack_h2(__half a, __half b) {
    __half2 h = __halves2half2(a, b);
    return *(uint32_t*)&h;
}
__device__ __forceinline__ uint32_t smem_u32(const void* p) {
    uint32_t a;
    asm("{ .reg .u64 t; cvta.to.shared.u64 t, %1; cvt.u32.u64 %0, t; }" : "=r"(a) : "l"(p));
    return a;
}
__device__ __forceinline__ void cpasync16(uint32_t dst, const void* src) {
    asm volatile("cp.async.cg.shared.global [%0], [%1], 16;" :: "r"(dst), "l"(src));
}
#define CP_COMMIT() asm volatile("cp.async.commit_group;" ::: "memory")
#define CP_WAIT0()  asm volatile("cp.async.wait_group 0;" ::: "memory")
#define CP_WAIT1()  asm volatile("cp.async.wait_group 1;" ::: "memory")

// ------------------- prepB: (W^T * 256) -> fp16 hi/lo ------------------------
__global__ __launch_bounds__(256) void prepB(
    const float* __restrict__ Wf, const float* __restrict__ Ws)
{
    int i = blockIdx.x * 256 + threadIdx.x;     // 192*768
    int n = i / 768, k = i - n * 768;
    float v = (n < 128) ? Wf[(size_t)k * 128 + n] : Ws[(size_t)k * 64 + (n - 128)];
    v *= 256.0f;                                 // keep residual in fp16 normal range
    __half hi = __float2half_rn(v);
    float r = v - __half2float(hi);
    g_Bhi[i] = hi;
    g_Blo[i] = __float2half_rn(r);
}

// ---------------------------------------------------------------------------
// gemmA via mma.sync, software-pipelined, 512 threads (16 warps, 4/SMSP).
// Warp grid 4x4: wr = rows 32*wr, wc = cols 48*wc (6 nf of 8 cols).
// f cols (<128): 2-term split; s cols (>=128): 3-term.
// A register-prefetched; B double-buffered cp.async.
// ---------------------------------------------------------------------------
#define SMA_HI 0
#define SMA_LO (128 * 144)
#define SMB(buf) (2 * 128 * 144 + (buf) * (2 * 192 * 144))
#define SMB_LO_OFF (192 * 144)
#define SM_TOTAL (2 * 128 * 144 + 2 * 2 * 192 * 144)   // 147456 B

__global__ __launch_bounds__(512) void gemmA_mma(
    const float* __restrict__ x, const float* __restrict__ bf,
    const float* __restrict__ bs, const float* __restrict__ sharp)
{
    extern __shared__ char sm[];
    const uint32_t smu = smem_u32(sm);
    const int tid = threadIdx.x, wid = tid >> 5, lane = tid & 31;
    const int b = blockIdx.y, nt = blockIdx.x;
    const int wr = wid & 3, wc = wid >> 2;          // 4 x 4 warp grid
    const int g = lane >> 2, tig = lane & 3;
    const bool haveLo = (wc >= 2);                  // warps touching s-cols

    const float* A = x + (size_t)b * 1025 * 768 + 768 + (size_t)nt * 128 * 768;
    const int am = tid >> 2, akb = (tid & 3) * 16;  // 4 float4 per thread
    const float* aptr = A + (size_t)am * 768 + akb;

    float acc[2][6][4];
    #pragma unroll
    for (int mf = 0; mf < 2; mf++)
        #pragma unroll
        for (int nf = 0; nf < 6; nf++)
            #pragma unroll
            for (int q = 0; q < 4; q++) acc[mf][nf][q] = 0.0f;

    float4 aPre[4];
    #pragma unroll
    for (int i = 0; i < 4; i++) aPre[i] = *(const float4*)(aptr + i * 4);
    #pragma unroll
    for (int j = 0; j < 3; j++) {
        int e = tid + j * 512;
        int n = e >> 3, u = e & 7;
        uint32_t doff = (uint32_t)(n * 144 + u * 16);
        cpasync16(smu + SMB(0) + doff, g_Bhi + (size_t)n * 768 + u * 8);
        cpasync16(smu + SMB(0) + SMB_LO_OFF + doff, g_Blo + (size_t)n * 768 + u * 8);
    }
    CP_COMMIT();

    #pragma unroll 1
    for (int ch = 0; ch < 12; ch++) {
        const int buf = ch & 1;
        // ---- convert prefetched A regs -> smem hi/lo ----
        #pragma unroll
        for (int i = 0; i < 4; i++) {
            float4 v = aPre[i];
            __half hx = __float2half_rn(v.x), hy = __float2half_rn(v.y);
            __half hz = __float2half_rn(v.z), hw = __float2half_rn(v.w);
            __half lx = __float2half_rn(v.x - __half2float(hx));
            __half ly = __float2half_rn(v.y - __half2float(hy));
            __half lz = __float2half_rn(v.z - __half2float(hz));
            __half lw = __float2half_rn(v.w - __half2float(hw));
            uint32_t off = am * 144 + (akb + i * 4) * 2;
            *(uint2*)(sm + SMA_HI + off) = make_uint2(pack_h2(hx, hy), pack_h2(hz, hw));
            *(uint2*)(sm + SMA_LO + off) = make_uint2(pack_h2(lx, ly), pack_h2(lz, lw));
        }
        // ---- prefetch chunk ch+1 (A->regs, B->other smem buf) ----
        if (ch < 11) {
            const int k1 = (ch + 1) * 64;
            #pragma unroll
            for (int i = 0; i < 4; i++) aPre[i] = *(const float4*)(aptr + k1 + i * 4);
            #pragma unroll
            for (int j = 0; j < 3; j++) {
                int e = tid + j * 512;
                int n = e >> 3, u = e & 7;
                uint32_t doff = (uint32_t)(n * 144 + u * 16);
                cpasync16(smu + SMB(buf ^ 1) + doff, g_Bhi + (size_t)n * 768 + k1 + u * 8);
                cpasync16(smu + SMB(buf ^ 1) + SMB_LO_OFF + doff, g_Blo + (size_t)n * 768 + k1 + u * 8);
            }
            CP_COMMIT();
            CP_WAIT1();
        } else {
            CP_WAIT0();
        }
        __syncthreads();

        const char* BH = sm + SMB(buf);
        const char* BL = BH + SMB_LO_OFF;
        #pragma unroll
        for (int ks = 0; ks < 4; ks++) {
            const int kk = ks * 16;
            uint32_t ahi[2][4], alo[2][4];
            #pragma unroll
            for (int mf = 0; mf < 2; mf++) {
                int r0 = (wr * 32 + mf * 16 + g) * 144 + (kk + tig * 2) * 2;
                int r1 = r0 + 8 * 144;
                ahi[mf][0] = *(const uint32_t*)(sm + SMA_HI + r0);
                ahi[mf][1] = *(const uint32_t*)(sm + SMA_HI + r1);
                ahi[mf][2] = *(const uint32_t*)(sm + SMA_HI + r0 + 16);
                ahi[mf][3] = *(const uint32_t*)(sm + SMA_HI + r1 + 16);
                if (haveLo) {
                    alo[mf][0] = *(const uint32_t*)(sm + SMA_LO + r0);
                    alo[mf][1] = *(const uint32_t*)(sm + SMA_LO + r1);
                    alo[mf][2] = *(const uint32_t*)(sm + SMA_LO + r0 + 16);
                    alo[mf][3] = *(const uint32_t*)(sm + SMA_LO + r1 + 16);
                }
            }
            #pragma unroll
            for (int nf = 0; nf < 6; nf++) {
                const int colBase = wc * 48 + nf * 8;
                int nb = (colBase + g) * 144 + (kk + tig * 2) * 2;
                uint32_t bh0 = *(const uint32_t*)(BH + nb);
                uint32_t bh1 = *(const uint32_t*)(BH + nb + 16);
                uint32_t bl0 = *(const uint32_t*)(BL + nb);
                uint32_t bl1 = *(const uint32_t*)(BL + nb + 16);
                #pragma unroll
                for (int mf = 0; mf < 2; mf++) {
                    mma16816(acc[mf][nf], ahi[mf][0], ahi[mf][1], ahi[mf][2], ahi[mf][3], bh0, bh1);
                    mma16816(acc[mf][nf], ahi[mf][0], ahi[mf][1], ahi[mf][2], ahi[mf][3], bl0, bl1);
                    if (haveLo && colBase >= 128)   // s-cols only: 3rd term
                        mma16816(acc[mf][nf], alo[mf][0], alo[mf][1], alo[mf][2], alo[mf][3], bh0, bh1);
                }
            }
        }
        __syncthreads();
    }

    // ---------------------------- epilogue ----------------------------------
    const float inv256 = 1.0f / 256.0f;
    const float scl = sharp[0] * 10.0f * LOG2E_F;   // sharpness/REG * log2(e)
    #pragma unroll
    for (int mf = 0; mf < 2; mf++) {
        #pragma unroll
        for (int nf = 0; nf < 6; nf++) {
            int c = wc * 48 + nf * 8 + tig * 2;
            int r0 = nt * 128 + wr * 32 + mf * 16 + g;
            int r1 = r0 + 8;
            float d0 = acc[mf][nf][0], d1 = acc[mf][nf][1];
            float d2 = acc[mf][nf][2], d3 = acc[mf][nf][3];
            if (c < 128) {
                float b0 = __ldg(bf + c), b1 = __ldg(bf + c + 1);
                *(float2*)(g_f + ((size_t)(b * 1024 + r0)) * 128 + c) =
                    make_float2(fmaf(d0, inv256, b0), fmaf(d1, inv256, b1));
                *(float2*)(g_f + ((size_t)(b * 1024 + r1)) * 128 + c) =
                    make_float2(fmaf(d2, inv256, b0), fmaf(d3, inv256, b1));
            } else {
                int k = c - 128;
                float b0 = __ldg(bs + k), b1 = __ldg(bs + k + 1);
                float* K0 = g_K + ((size_t)(b * 64 + k)) * 1024;
                float* K1 = g_K + ((size_t)(b * 64 + k + 1)) * 1024;
                K0[r0] = fmaf(d0, inv256, b0) * scl;
                K1[r0] = fmaf(d1, inv256, b1) * scl;
                K0[r1] = fmaf(d2, inv256, b0) * scl;
                K1[r1] = fmaf(d3, inv256, b1) * scl;
            }
        }
    }
}

// ------------- expprep: rowmax + exp2 + rowsum -> initial r ------------------
__global__ __launch_bounds__(256) void expprep()
{
    const int row = blockIdx.x;              // b*64 + k
    float4* p = (float4*)(g_K + ((size_t)row << 10));
    const int t = threadIdx.x;
    float4 v = p[t];
    __shared__ float red[8];
    __shared__ float s_bm;
    float mx = fmaxf(fmaxf(v.x, v.y), fmaxf(v.z, v.w));
    mx = warpMax(mx);
    if ((t & 31) == 0) red[t >> 5] = mx;
    __syncthreads();
    if (t == 0) {
        float mm = red[0];
        #pragma unroll
        for (int i = 1; i < 8; i++) mm = fmaxf(mm, red[i]);
        s_bm = mm;
    }
    __syncthreads();
    const float m = s_bm;
    v.x = exp2_fma(v.x - m); v.y = exp2_fma(v.y - m);
    v.z = exp2_fma(v.z - m); v.w = exp2_fma(v.w - m);
    p[t] = v;
    float s = (v.x + v.y) + (v.z + v.w);
    s = warpSum(s);
    if ((t & 31) == 0) red[t >> 5] = s;
    __syncthreads();
    if (t == 0) {
        float tot = 0.0f;
        #pragma unroll
        for (int i = 0; i < 8; i++) tot += red[i];
        g_r[(row >> 6) * 65 + (row & 63)] = (1.0f / 65.0f) / tot;
        if ((row & 63) == 0) g_r[(row >> 6) * 65 + 64] = (1.0f / 65.0f) / 1024.0f;
    }
}

// ------------- fused Sinkhorn: 5 c-updates + 4 r-updates, one launch ---------
__global__ __launch_bounds__(1024) void sinkhorn()
{
    const int b = blockIdx.x;
    const int t = threadIdx.x, w = t >> 5, l = t & 31;
    __shared__ float cs[1024];
    __shared__ float rs[72];
    __shared__ float red[32];
    if (t < 65) rs[t] = g_r[b * 65 + t];
    __syncthreads();
    const float* Kb = g_K + ((size_t)b << 16);

    #pragma unroll 1
    for (int it = 0; it < 5; it++) {
        // c-update (thread = column t), 8 independent chains
        const float* col = Kb + t;
        float a0 = rs[64], a1 = 0.f, a2 = 0.f, a3 = 0.f;
        float a4 = 0.f, a5 = 0.f, a6 = 0.f, a7 = 0.f;
        #pragma unroll
        for (int k = 0; k < 64; k += 8) {
            a0 = fmaf(col[(size_t)(k + 0) << 10], rs[k + 0], a0);
            a1 = fmaf(col[(size_t)(k + 1) << 10], rs[k + 1], a1);
            a2 = fmaf(col[(size_t)(k + 2) << 10], rs[k + 2], a2);
            a3 = fmaf(col[(size_t)(k + 3) << 10], rs[k + 3], a3);
            a4 = fmaf(col[(size_t)(k + 4) << 10], rs[k + 4], a4);
            a5 = fmaf(col[(size_t)(k + 5) << 10], rs[k + 5], a5);
            a6 = fmaf(col[(size_t)(k + 6) << 10], rs[k + 6], a6);
            a7 = fmaf(col[(size_t)(k + 7) << 10], rs[k + 7], a7);
        }
        float cv = (1.0f / 1024.0f) /
                   (((a0 + a1) + (a2 + a3)) + ((a4 + a5) + (a6 + a7)));
        cs[t] = cv;
        float sw = warpSum(cv);
        if (l == 0) red[w] = sw;
        __syncthreads();
        if (it < 4) {
            if (t == 0) {
                float s = 0.0f;
                #pragma unroll
                for (int i = 0; i < 32; i++) s += red[i];
                rs[64] = (1.0f / 65.0f) / s;
            }
            // r-update (warp w -> rows w, w+32), 8 chains
            #pragma unroll
            for (int rr = 0; rr < 2; rr++) {
                int k = w + rr * 32;
                const float* row = Kb + ((size_t)k << 10);
                float d0 = 0.f, d1 = 0.f, d2 = 0.f, d3 = 0.f;
                float d4 = 0.f, d5 = 0.f, d6 = 0.f, d7 = 0.f;
                #pragma unroll
                for (int n0 = 0; n0 < 1024; n0 += 256) {
                    d0 = fmaf(row[n0 + l],        cs[n0 + l],        d0);
                    d1 = fmaf(row[n0 + l + 32],   cs[n0 + l + 32],   d1);
                    d2 = fmaf(row[n0 + l + 64],   cs[n0 + l + 64],   d2);
                    d3 = fmaf(row[n0 + l + 96],   cs[n0 + l + 96],   d3);
                    d4 = fmaf(row[n0 + l + 128],  cs[n0 + l + 128],  d4);
                    d5 = fmaf(row[n0 + l + 160],  cs[n0 + l + 160],  d5);
                    d6 = fmaf(row[n0 + l + 192],  cs[n0 + l + 192],  d6);
                    d7 = fmaf(row[n0 + l + 224],  cs[n0 + l + 224],  d7);
                }
                float d = warpSum((((d0 + d1) + (d2 + d3)) + ((d4 + d5) + (d6 + d7))));
                if (l == 0) rs[k] = (1.0f / 65.0f) / d;
            }
            __syncthreads();
        }
    }
    g_c[b * 1024 + t] = cs[t];
    if (t < 65) g_r[b * 65 + t] = rs[t];
}

// ---------------------------------------------------------------------------
// GEMM C: partial (64x128) = p_slice @ f_slice, p materialized as K~ * r * c.
// ---------------------------------------------------------------------------
__global__ __launch_bounds__(256) void gemmC()
{
    const int b = blockIdx.y, sp = blockIdx.x;
    const int tid = threadIdx.x;
    const int tx = tid & 15, ty = tid >> 4;
    __shared__ float ps[64][33];
    __shared__ float fs[32][128];

    const int n0 = sp * 128;
    float acc[4][8];
    #pragma unroll
    for (int i = 0; i < 4; i++)
        #pragma unroll
        for (int j = 0; j < 8; j++) acc[i][j] = 0.0f;
    float psum = 0.0f;

    for (int c0 = 0; c0 < 128; c0 += 32) {
        __syncthreads();
        #pragma unroll
        for (int j = 0; j < 2; j++) {
            int idx4 = tid + j * 256;
            int k = idx4 >> 3;
            int nn4 = (idx4 & 7) * 4;
            float4 kv = *(const float4*)(g_K + ((size_t)(b * 64 + k)) * 1024 + n0 + c0 + nn4);
            float4 cv = *(const float4*)(g_c + b * 1024 + n0 + c0 + nn4);
            float rv = __ldg(&g_r[b * 65 + k]);
            ps[k][nn4 + 0] = kv.x * cv.x * rv;
            ps[k][nn4 + 1] = kv.y * cv.y * rv;
            ps[k][nn4 + 2] = kv.z * cv.z * rv;
            ps[k][nn4 + 3] = kv.w * cv.w * rv;
        }
        #pragma unroll
        for (int j = 0; j < 4; j++) {
            int idx4 = tid + j * 256;
            int nn = idx4 >> 5;
            int c4 = (idx4 & 31) * 4;
            *(float4*)&fs[nn][c4] =
                *(const float4*)(g_f + ((size_t)(b * 1024 + n0 + c0 + nn)) * 128 + c4);
        }
        __syncthreads();

        #pragma unroll
        for (int nn = 0; nn < 32; nn++) {
            float a4[4];
            #pragma unroll
            for (int i = 0; i < 4; i++) a4[i] = ps[ty * 4 + i][nn];
            float4 b0 = *(const float4*)&fs[nn][tx * 8];
            float4 b1 = *(const float4*)&fs[nn][tx * 8 + 4];
            float b8[8] = {b0.x, b0.y, b0.z, b0.w, b1.x, b1.y, b1.z, b1.w};
            #pragma unroll
            for (int i = 0; i < 4; i++)
                #pragma unroll
                for (int j = 0; j < 8; j++)
                    acc[i][j] = fmaf(a4[i], b8[j], acc[i][j]);
        }

        if (tid < 64) {
            float s = 0.0f;
            #pragma unroll
            for (int nn = 0; nn < 32; nn++) s += ps[tid][nn];
            psum += s;
        }
    }

    #pragma unroll
    for (int i = 0; i < 4; i++) {
        float* dst = g_vpart + (((size_t)(b * 8 + sp) * 64) + ty * 4 + i) * 128 + tx * 8;
        *(float4*)(dst)     = make_float4(acc[i][0], acc[i][1], acc[i][2], acc[i][3]);
        *(float4*)(dst + 4) = make_float4(acc[i][4], acc[i][5], acc[i][6], acc[i][7]);
    }
    if (tid < 64) g_pspart[(b * 8 + sp) * 64 + tid] = psum;
}

// --- finalK: t = x0@Wt + bt fused with split-K reduction + L2 normalize -----
__global__ __launch_bounds__(1024) void finalK(
    const float* __restrict__ x, const float* __restrict__ Wt,
    const float* __restrict__ bt, const float* __restrict__ anchors,
    float* __restrict__ out)
{
    const int b = blockIdx.x, t = threadIdx.x;
    float* orow = out + (size_t)b * 8448;
    __shared__ float xs[768];
    if (t < 768) xs[t] = x[(size_t)b * 1025 * 768 + t];
    __syncthreads();

    float ss = 0.0f;
    // v part: reduce split-K partials
    #pragma unroll
    for (int j = 0; j < 8; j++) {
        int e = t + j * 1024;
        int k = e >> 7, c = e & 127;
        float s2 = 0.0f, sps = 0.0f;
        #pragma unroll
        for (int sp = 0; sp < 8; sp++) {
            s2  += g_vpart[(((size_t)(b * 8 + sp) * 64) + k) * 128 + c];
            sps += g_pspart[(b * 8 + sp) * 64 + k];
        }
        float val = 2.0f * s2 - sps * anchors[k * 128 + c];
        orow[256 + e] = val;
        ss += val * val;
    }
    // t part (threads 0..255)
    if (t < 256) {
        float tv = bt[t];
        #pragma unroll 8
        for (int d = 0; d < 768; d++) tv = fmaf(xs[d], Wt[(size_t)d * 256 + t], tv);
        orow[t] = tv;
        ss += tv * tv;
    }

    __shared__ float red[32];
    __shared__ float s_inv;
    float w = warpSum(ss);
    if ((t & 31) == 0) red[t >> 5] = w;
    __syncthreads();
    if (t < 32) {
        float v = red[t];
        v = warpSum(v);
        if (t == 0) s_inv = 1.0f / fmaxf(sqrtf(v), 1e-12f);
    }
    __syncthreads();
    const float inv = s_inv;
    for (int idx = t; idx < 8448; idx += 1024) orow[idx] *= inv;
}

// ---------------------------------------------------------------------------
extern "C" void kernel_launch(void* const* d_in, const int* in_sizes, int n_in,
                              void* d_out, int out_size)
{
    const float* x       = (const float*)d_in[0];
    const float* Wf      = (const float*)d_in[1];
    const float* bf      = (const float*)d_in[2];
    const float* Ws      = (const float*)d_in[3];
    const float* bs      = (const float*)d_in[4];
    const float* Wt      = (const float*)d_in[5];
    const float* bt      = (const float*)d_in[6];
    const float* anchors = (const float*)d_in[7];
    // d_in[8] = dust_bin: constant row shift, cancels in the transport plan.
    const float* sharp   = (const float*)d_in[9];
    float* out = (float*)d_out;

    static int smem_set = 0;
    if (!smem_set) {
        cudaFuncSetAttribute(gemmA_mma, cudaFuncAttributeMaxDynamicSharedMemorySize, SM_TOTAL);
        smem_set = 1;
    }

    prepB<<<576, 256>>>(Wf, Ws);
    gemmA_mma<<<dim3(8, 32), 512, SM_TOTAL>>>(x, bf, bs, sharp);
    expprep<<<2048, 256>>>();
    sinkhorn<<<32, 1024>>>();
    gemmC<<<dim3(8, 32), 256>>>();
    finalK<<<32, 1024>>>(x, Wt, bt, anchors, out);
}